// round 14
// baseline (speedup 1.0000x reference)
#include <cuda_runtime.h>

// BSplineKAN: y[b,c] = sum_i cp[c,i] * N_{i,3}(clip(x[b,c], -0.99, 0.99))
// Uniform knots on [-1,1] (12 knots, h=2/11) => cardinal uniform cubic B-spline.
// Per (channel, interval j) the result is a cubic in u: precompute poly table A.
//
// R8: the table gather's bank group was (j mod 8) for ALL lanes -> ~2x LDS
// conflict overhead (L1 pipe 80%). Swizzle slot by channel-row m = c>>2:
// slot = c*16 + (j ^ (m & 7)), spreading lanes near-uniformly over the 8
// 16B bank groups.

#define NC 64          // channels
#define NP 8           // control points per channel
#define NJ 11          // intervals (12 knots - 1)
#define TSTRIDE 16     // padded j-stride for the table

// Scratch: polynomial coefficient table A[c][swz(j)] = (a0,a1,a2,a3).
__device__ float4 g_A[NC * TSTRIDE];

__device__ __forceinline__ int table_slot(int c, int j) {
    return c * TSTRIDE + (j ^ ((c >> 2) & 7));
}

__global__ void bspline_setup_kernel(const float* __restrict__ cp) {
    int idx = blockIdx.x * blockDim.x + threadIdx.x;
    if (idx >= NC * TSTRIDE) return;
    int c = idx / TSTRIDE;
    int s = idx % TSTRIDE;
    int j = s ^ ((c >> 2) & 7);          // inverse of the swizzle
    float4 a = make_float4(0.f, 0.f, 0.f, 0.f);
    if (j < NJ) {
        float p[4];
        #pragma unroll
        for (int k = 0; k < 4; k++) {
            int i = j - 3 + k;                       // basis index
            p[k] = (i >= 0 && i < NP) ? cp[c * NP + i] : 0.0f;
        }
        // result on interval j:  a0 + a1 u + a2 u^2 + a3 u^3
        a.x = (p[0] + 4.0f * p[1] + p[2]) * (1.0f / 6.0f);
        a.y = (p[2] - p[0]) * 0.5f;
        a.z = (p[0] - 2.0f * p[1] + p[2]) * 0.5f;
        a.w = (p[3] - p[0] + 3.0f * (p[1] - p[2])) * (1.0f / 6.0f);
    }
    g_A[idx] = a;                         // g_A stored pre-swizzled
}

__global__ void __launch_bounds__(256)
bspline_main_kernel(const float4* __restrict__ x4,
                    float4* __restrict__ o4,
                    int n4) {
    __shared__ float4 sA[NC * TSTRIDE];   // 16 KB, swizzled layout
    #pragma unroll
    for (int i = threadIdx.x; i < NC * TSTRIDE; i += 256)
        sA[i] = g_A[i];
    __syncthreads();

    const int stride = gridDim.x * blockDim.x;
    for (int i = blockIdx.x * blockDim.x + threadIdx.x; i < n4; i += stride) {
        float4 xv = x4[i];
        // channel base of this float4: (4*i) mod 64
        int cbase = (i & 15) << 2;

        float xa[4] = {xv.x, xv.y, xv.z, xv.w};
        float ra[4];
        #pragma unroll
        for (int k = 0; k < 4; k++) {
            float xc = fminf(fmaxf(xa[k], -0.99f), 0.99f);
            float t  = (xc + 1.0f) * 5.5f;          // (x+1)/h, h = 2/11
            int   j  = (int)t;                       // 0..10 guaranteed by clip
            float u  = t - (float)j;
            float4 a = sA[table_slot(cbase + k, j)];
            ra[k] = fmaf(fmaf(fmaf(a.w, u, a.z), u, a.y), u, a.x);
        }
        o4[i] = make_float4(ra[0], ra[1], ra[2], ra[3]);
    }
}

extern "C" void kernel_launch(void* const* d_in, const int* in_sizes, int n_in,
                              void* d_out, int out_size) {
    const float* x  = (const float*)d_in[0];        // [262144, 64] f32
    const float* cp = (const float*)d_in[1];        // [64, 8] f32
    float* out = (float*)d_out;

    // 1) Build the per-(channel, interval) cubic coefficient table (swizzled).
    bspline_setup_kernel<<<(NC * TSTRIDE + 255) / 256, 256>>>(cp);

    // 2) Streaming evaluation, float4-vectorized.
    int n4 = out_size / 4;                           // elements / 4
    int blocks = 148 * 32;
    int max_blocks = (n4 + 255) / 256;
    if (blocks > max_blocks) blocks = max_blocks;
    bspline_main_kernel<<<blocks, 256>>>(
        (const float4*)x, (float4*)out, n4);
}

// round 15
// speedup vs baseline: 1.0063x; 1.0063x over previous
#include <cuda_runtime.h>

// BSplineKAN: y[b,c] = sum_i cp[c,i] * N_{i,3}(clip(x[b,c], -0.99, 0.99))
// Uniform knots on [-1,1] (12 knots, h=2/11) => cardinal uniform cubic B-spline.
// Per (channel, interval j) the result is a cubic in u: precompute poly table A.
//
// R8: the table gather's bank group was (j mod 8) for ALL lanes -> ~2x LDS
// conflict overhead (L1 pipe 80%). Swizzle slot by channel-row m = c>>2:
// slot = c*16 + (j ^ (m & 7)), spreading lanes near-uniformly over the 8
// 16B bank groups.

#define NC 64          // channels
#define NP 8           // control points per channel
#define NJ 11          // intervals (12 knots - 1)
#define TSTRIDE 16     // padded j-stride for the table

// Scratch: polynomial coefficient table A[c][swz(j)] = (a0,a1,a2,a3).
__device__ float4 g_A[NC * TSTRIDE];

__device__ __forceinline__ int table_slot(int c, int j) {
    return c * TSTRIDE + (j ^ ((c >> 2) & 7));
}

__global__ void bspline_setup_kernel(const float* __restrict__ cp) {
    int idx = blockIdx.x * blockDim.x + threadIdx.x;
    if (idx >= NC * TSTRIDE) return;
    int c = idx / TSTRIDE;
    int s = idx % TSTRIDE;
    int j = s ^ ((c >> 2) & 7);          // inverse of the swizzle
    float4 a = make_float4(0.f, 0.f, 0.f, 0.f);
    if (j < NJ) {
        float p[4];
        #pragma unroll
        for (int k = 0; k < 4; k++) {
            int i = j - 3 + k;                       // basis index
            p[k] = (i >= 0 && i < NP) ? cp[c * NP + i] : 0.0f;
        }
        // result on interval j:  a0 + a1 u + a2 u^2 + a3 u^3
        a.x = (p[0] + 4.0f * p[1] + p[2]) * (1.0f / 6.0f);
        a.y = (p[2] - p[0]) * 0.5f;
        a.z = (p[0] - 2.0f * p[1] + p[2]) * 0.5f;
        a.w = (p[3] - p[0] + 3.0f * (p[1] - p[2])) * (1.0f / 6.0f);
    }
    g_A[idx] = a;                         // g_A stored pre-swizzled
}

__global__ void __launch_bounds__(256)
bspline_main_kernel(const float4* __restrict__ x4,
                    float4* __restrict__ o4,
                    int n4) {
    __shared__ float4 sA[NC * TSTRIDE];   // 16 KB, swizzled layout
    #pragma unroll
    for (int i = threadIdx.x; i < NC * TSTRIDE; i += 256)
        sA[i] = g_A[i];
    __syncthreads();

    const int stride = gridDim.x * blockDim.x;
    for (int i = blockIdx.x * blockDim.x + threadIdx.x; i < n4; i += stride) {
        float4 xv = x4[i];
        // channel base of this float4: (4*i) mod 64
        int cbase = (i & 15) << 2;

        float xa[4] = {xv.x, xv.y, xv.z, xv.w};
        float ra[4];
        #pragma unroll
        for (int k = 0; k < 4; k++) {
            float xc = fminf(fmaxf(xa[k], -0.99f), 0.99f);
            float t  = (xc + 1.0f) * 5.5f;          // (x+1)/h, h = 2/11
            int   j  = (int)t;                       // 0..10 guaranteed by clip
            float u  = t - (float)j;
            float4 a = sA[table_slot(cbase + k, j)];
            ra[k] = fmaf(fmaf(fmaf(a.w, u, a.z), u, a.y), u, a.x);
        }
        o4[i] = make_float4(ra[0], ra[1], ra[2], ra[3]);
    }
}

extern "C" void kernel_launch(void* const* d_in, const int* in_sizes, int n_in,
                              void* d_out, int out_size) {
    const float* x  = (const float*)d_in[0];        // [262144, 64] f32
    const float* cp = (const float*)d_in[1];        // [64, 8] f32
    float* out = (float*)d_out;

    // 1) Build the per-(channel, interval) cubic coefficient table (swizzled).
    bspline_setup_kernel<<<(NC * TSTRIDE + 255) / 256, 256>>>(cp);

    // 2) Streaming evaluation, float4-vectorized.
    int n4 = out_size / 4;                           // elements / 4
    int blocks = 148 * 32;
    int max_blocks = (n4 + 255) / 256;
    if (blocks > max_blocks) blocks = max_blocks;
    bspline_main_kernel<<<blocks, 256>>>(
        (const float4*)x, (float4*)out, n4);
}

// round 16
// speedup vs baseline: 1.0073x; 1.0009x over previous
#include <cuda_runtime.h>

// BSplineKAN: y[b,c] = sum_i cp[c,i] * N_{i,3}(clip(x[b,c], -0.99, 0.99))
// Uniform knots on [-1,1] (12 knots, h=2/11) => cardinal uniform cubic B-spline.
// Per (channel, interval j) the result is a cubic in u: precompute poly table A.
//
// R8: the table gather's bank group was (j mod 8) for ALL lanes -> ~2x LDS
// conflict overhead (L1 pipe 80%). Swizzle slot by channel-row m = c>>2:
// slot = c*16 + (j ^ (m & 7)), spreading lanes near-uniformly over the 8
// 16B bank groups.

#define NC 64          // channels
#define NP 8           // control points per channel
#define NJ 11          // intervals (12 knots - 1)
#define TSTRIDE 16     // padded j-stride for the table

// Scratch: polynomial coefficient table A[c][swz(j)] = (a0,a1,a2,a3).
__device__ float4 g_A[NC * TSTRIDE];

__device__ __forceinline__ int table_slot(int c, int j) {
    return c * TSTRIDE + (j ^ ((c >> 2) & 7));
}

__global__ void bspline_setup_kernel(const float* __restrict__ cp) {
    int idx = blockIdx.x * blockDim.x + threadIdx.x;
    if (idx >= NC * TSTRIDE) return;
    int c = idx / TSTRIDE;
    int s = idx % TSTRIDE;
    int j = s ^ ((c >> 2) & 7);          // inverse of the swizzle
    float4 a = make_float4(0.f, 0.f, 0.f, 0.f);
    if (j < NJ) {
        float p[4];
        #pragma unroll
        for (int k = 0; k < 4; k++) {
            int i = j - 3 + k;                       // basis index
            p[k] = (i >= 0 && i < NP) ? cp[c * NP + i] : 0.0f;
        }
        // result on interval j:  a0 + a1 u + a2 u^2 + a3 u^3
        a.x = (p[0] + 4.0f * p[1] + p[2]) * (1.0f / 6.0f);
        a.y = (p[2] - p[0]) * 0.5f;
        a.z = (p[0] - 2.0f * p[1] + p[2]) * 0.5f;
        a.w = (p[3] - p[0] + 3.0f * (p[1] - p[2])) * (1.0f / 6.0f);
    }
    g_A[idx] = a;                         // g_A stored pre-swizzled
}

__global__ void __launch_bounds__(256)
bspline_main_kernel(const float4* __restrict__ x4,
                    float4* __restrict__ o4,
                    int n4) {
    __shared__ float4 sA[NC * TSTRIDE];   // 16 KB, swizzled layout
    #pragma unroll
    for (int i = threadIdx.x; i < NC * TSTRIDE; i += 256)
        sA[i] = g_A[i];
    __syncthreads();

    const int stride = gridDim.x * blockDim.x;
    for (int i = blockIdx.x * blockDim.x + threadIdx.x; i < n4; i += stride) {
        float4 xv = x4[i];
        // channel base of this float4: (4*i) mod 64
        int cbase = (i & 15) << 2;

        float xa[4] = {xv.x, xv.y, xv.z, xv.w};
        float ra[4];
        #pragma unroll
        for (int k = 0; k < 4; k++) {
            float xc = fminf(fmaxf(xa[k], -0.99f), 0.99f);
            float t  = (xc + 1.0f) * 5.5f;          // (x+1)/h, h = 2/11
            int   j  = (int)t;                       // 0..10 guaranteed by clip
            float u  = t - (float)j;
            float4 a = sA[table_slot(cbase + k, j)];
            ra[k] = fmaf(fmaf(fmaf(a.w, u, a.z), u, a.y), u, a.x);
        }
        o4[i] = make_float4(ra[0], ra[1], ra[2], ra[3]);
    }
}

extern "C" void kernel_launch(void* const* d_in, const int* in_sizes, int n_in,
                              void* d_out, int out_size) {
    const float* x  = (const float*)d_in[0];        // [262144, 64] f32
    const float* cp = (const float*)d_in[1];        // [64, 8] f32
    float* out = (float*)d_out;

    // 1) Build the per-(channel, interval) cubic coefficient table (swizzled).
    bspline_setup_kernel<<<(NC * TSTRIDE + 255) / 256, 256>>>(cp);

    // 2) Streaming evaluation, float4-vectorized.
    int n4 = out_size / 4;                           // elements / 4
    int blocks = 148 * 32;
    int max_blocks = (n4 + 255) / 256;
    if (blocks > max_blocks) blocks = max_blocks;
    bspline_main_kernel<<<blocks, 256>>>(
        (const float4*)x, (float4*)out, n4);
}

// round 17
// speedup vs baseline: 1.1383x; 1.1301x over previous
#include <cuda_runtime.h>

// BSplineKAN: y[b,c] = sum_i cp[c,i] * N_{i,3}(clip(x[b,c], -0.99, 0.99))
// Uniform knots => cardinal cubic B-spline => per (channel, interval) cubic
// poly table A[c][j] = (a0,a1,a2,a3); y = a0 + a1 u + a2 u^2 + a3 u^3.
//
// R16: random-j LDS.128 gathers cost ~11.6 cyc (4 phases x E[max 8-in-8]~2.9).
// Fix: replicate each table entry 8x across the 8 16B bank-groups of a 128B
// row; lane reads replica (lane&7) -> every phase conflict-free -> 4 cyc.

#define NC 64
#define NP 8
#define NJ 11
#define NENT (NC * NJ)          // 704 compact entries
#define SMEM_BYTES (NENT * 128) // 90112: 8 float4 replicas per entry

__device__ float4 g_Ac[NENT];   // compact coefficient table

__global__ void bspline_setup_kernel(const float* __restrict__ cp) {
    int idx = blockIdx.x * blockDim.x + threadIdx.x;
    if (idx >= NENT) return;
    int c = idx / NJ;
    int j = idx % NJ;
    float p[4];
    #pragma unroll
    for (int k = 0; k < 4; k++) {
        int i = j - 3 + k;
        p[k] = (i >= 0 && i < NP) ? cp[c * NP + i] : 0.0f;
    }
    float4 a;
    a.x = (p[0] + 4.0f * p[1] + p[2]) * (1.0f / 6.0f);
    a.y = (p[2] - p[0]) * 0.5f;
    a.z = (p[0] - 2.0f * p[1] + p[2]) * 0.5f;
    a.w = (p[3] - p[0] + 3.0f * (p[1] - p[2])) * (1.0f / 6.0f);
    g_Ac[idx] = a;
}

__device__ __forceinline__ float4 ldcs4(const float4* p) {
    float4 v;
    asm volatile("ld.global.cs.v4.f32 {%0,%1,%2,%3}, [%4];"
                 : "=f"(v.x), "=f"(v.y), "=f"(v.z), "=f"(v.w) : "l"(p));
    return v;
}
__device__ __forceinline__ void stcs4(float4* p, float4 v) {
    asm volatile("st.global.cs.v4.f32 [%0], {%1,%2,%3,%4};"
                 :: "l"(p), "f"(v.x), "f"(v.y), "f"(v.z), "f"(v.w) : "memory");
}

__global__ void __launch_bounds__(256, 2)
bspline_main_kernel(const float4* __restrict__ x4,
                    float4* __restrict__ o4,
                    int n4) {
    extern __shared__ float4 sTab[];   // [NENT * 8] : 8 bank-group replicas
    for (int i = threadIdx.x; i < NENT * 8; i += blockDim.x)
        sTab[i] = g_Ac[i >> 3];
    __syncthreads();

    const int lane8 = threadIdx.x & 7;           // own bank-group replica
    const int S = gridDim.x * blockDim.x;        // multiple of 16
    int i0 = blockIdx.x * blockDim.x + threadIdx.x;
    // channel base of any handled float4: (4*i) mod 64 — invariant across
    // the grid stride since S % 16 == 0.
    const int cbase = (i0 & 15) << 2;
    const int row0 = (cbase * NJ) * 8 + lane8;   // base slot for k=0

    for (int i = i0; i < n4; i += 4 * S) {
        float4 xv[4];
        int    idxq[4];
        bool   ok[4];
        #pragma unroll
        for (int q = 0; q < 4; q++) {
            idxq[q] = i + q * S;
            ok[q] = idxq[q] < n4;
            if (ok[q]) xv[q] = ldcs4(x4 + idxq[q]);
        }
        #pragma unroll
        for (int q = 0; q < 4; q++) {
            if (!ok[q]) continue;
            float xa[4] = {xv[q].x, xv[q].y, xv[q].z, xv[q].w};
            float ra[4];
            #pragma unroll
            for (int k = 0; k < 4; k++) {
                float xc = fminf(fmaxf(xa[k], -0.99f), 0.99f);
                float t  = (xc + 1.0f) * 5.5f;       // (x+1)/h, h = 2/11
                int   j  = (int)t;                    // 0..10
                float u  = t - (float)j;
                float4 a = sTab[row0 + (k * NJ + j) * 8];
                ra[k] = fmaf(fmaf(fmaf(a.w, u, a.z), u, a.y), u, a.x);
            }
            stcs4(o4 + idxq[q], make_float4(ra[0], ra[1], ra[2], ra[3]));
        }
    }
}

extern "C" void kernel_launch(void* const* d_in, const int* in_sizes, int n_in,
                              void* d_out, int out_size) {
    const float* x  = (const float*)d_in[0];     // [262144, 64] f32
    const float* cp = (const float*)d_in[1];     // [64, 8] f32
    float* out = (float*)d_out;

    bspline_setup_kernel<<<(NENT + 255) / 256, 256>>>(cp);

    static int attr_set = 0;
    if (!attr_set) {
        cudaFuncSetAttribute(bspline_main_kernel,
                             cudaFuncAttributeMaxDynamicSharedMemorySize,
                             SMEM_BYTES);
        attr_set = 1;
    }

    int n4 = out_size / 4;
    int blocks = 148 * 2;                        // 2 CTAs/SM (88KB smem each)
    bspline_main_kernel<<<blocks, 256, SMEM_BYTES>>>(
        (const float4*)x, (float4*)out, n4);
}